// round 10
// baseline (speedup 1.0000x reference)
#include <cuda_runtime.h>

#define N_NODES 100000
#define N_EDGES 400000
#define IN_F 128
#define HID 1024
#define OUT_F 64

// Scratch (static device globals — referenced directly by device code only)
__device__ int   g_is64;
__device__ int   g_ei32[2 * N_EDGES];              // normalized edge index
__device__ float g_dinv[N_NODES];
__device__ float g_agg1[(size_t)N_NODES * IN_F];   //  51.2 MB
__device__ float g_h1[(size_t)N_NODES * HID];      // 409.6 MB
__device__ float g_p[(size_t)N_NODES * OUT_F];     //  25.6 MB

template <int TAG>
__device__ __forceinline__ float* buf() {
    if constexpr (TAG == 0) return g_agg1;
    else if constexpr (TAG == 1) return g_h1;
    else return g_p;
}

// ---------------------------------------------------------------------------
// Detect whether edge_index is int64 or int32. If int64 (values < 2^31,
// little-endian), every odd 32-bit word is zero. Sample 512 odd words.
__global__ void k_detect(const int* __restrict__ raw) {
    __shared__ int any_nonzero;
    if (threadIdx.x == 0) any_nonzero = 0;
    __syncthreads();
    int idx = 1 + 2 * (threadIdx.x * (N_EDGES / 512));   // odd words < 2*N_EDGES
    if (raw[idx] != 0) atomicOr(&any_nonzero, 1);
    __syncthreads();
    if (threadIdx.x == 0) g_is64 = any_nonzero ? 0 : 1;
}

// Normalize to int32 [src(0..E-1), dst(E..2E-1)]
__global__ void k_convert(const int* __restrict__ raw) {
    int e = blockIdx.x * blockDim.x + threadIdx.x;
    if (e < 2 * N_EDGES) {
        int is64 = g_is64;
        g_ei32[e] = is64 ? raw[2 * e] : raw[e];
    }
}

// ---------------------------------------------------------------------------
__global__ void k_init_deg() {
    int i = blockIdx.x * blockDim.x + threadIdx.x;
    if (i < N_NODES) g_dinv[i] = 1.0f;   // self-loop weight
}

__global__ void k_deg_edges(const float* __restrict__ ew) {
    int e = blockIdx.x * blockDim.x + threadIdx.x;
    if (e < N_EDGES) {
        int d = g_ei32[N_EDGES + e];
        atomicAdd(&g_dinv[d], ew[e]);
    }
}

__global__ void k_dinv() {
    int i = blockIdx.x * blockDim.x + threadIdx.x;
    if (i < N_NODES) {
        float v = g_dinv[i];
        g_dinv[i] = (v > 0.f) ? rsqrtf(v) : 0.f;
    }
}

// g_agg1[i][f] = x[i][f] * dinv[i]^2        (self-loop term, layer 1)
__global__ void k_selfloop1(const float* __restrict__ x) {
    int idx = blockIdx.x * blockDim.x + threadIdx.x;   // float4 index
    const int total = N_NODES * (IN_F / 4);
    if (idx >= total) return;
    int node = idx / (IN_F / 4);
    float di = g_dinv[node];
    float s  = di * di;
    float4 v = ((const float4*)x)[idx];
    float4 o;
    o.x = v.x * s; o.y = v.y * s; o.z = v.z * s; o.w = v.w * s;
    ((float4*)g_agg1)[idx] = o;
}

// out[i][f] = g_p[i][f] * dinv[i]^2 + b2[f]  (self-loop term + bias, layer 2)
__global__ void k_selfloop2(const float* __restrict__ b2,
                            float* __restrict__ out) {
    int idx = blockIdx.x * blockDim.x + threadIdx.x;
    const int total = N_NODES * (OUT_F / 4);
    if (idx >= total) return;
    int node = idx / (OUT_F / 4);
    int f4   = idx % (OUT_F / 4);
    float di = g_dinv[node];
    float s  = di * di;
    float4 v = ((const float4*)g_p)[idx];
    float4 b = ((const float4*)b2)[f4];
    float4 o;
    o.x = v.x * s + b.x; o.y = v.y * s + b.y;
    o.z = v.z * s + b.z; o.w = v.w * s + b.w;
    ((float4*)out)[idx] = o;
}

// warp-per-edge scatter, layer 1: g_agg1[dst] += norm * x[src]  (128 feats)
__global__ void k_scatter1(const float* __restrict__ ew,
                           const float* __restrict__ x) {
    int warp = (blockIdx.x * blockDim.x + threadIdx.x) >> 5;
    int lane = threadIdx.x & 31;
    if (warp >= N_EDGES) return;
    int s = 0, d = 0;
    float nrm = 0.f;
    if (lane == 0) {
        s = g_ei32[warp];
        d = g_ei32[N_EDGES + warp];
        nrm = g_dinv[s] * ew[warp] * g_dinv[d];
    }
    s   = __shfl_sync(0xffffffffu, s, 0);
    d   = __shfl_sync(0xffffffffu, d, 0);
    nrm = __shfl_sync(0xffffffffu, nrm, 0);

    const float4* xs = (const float4*)(x + (long long)s * IN_F);
    float*        od = g_agg1 + (long long)d * IN_F;
    float4 v = xs[lane];
    atomicAdd(&od[lane * 4 + 0], v.x * nrm);
    atomicAdd(&od[lane * 4 + 1], v.y * nrm);
    atomicAdd(&od[lane * 4 + 2], v.z * nrm);
    atomicAdd(&od[lane * 4 + 3], v.w * nrm);
}

// warp-per-edge scatter, layer 2: out[dst] += norm * g_p[src]  (64 feats)
__global__ void k_scatter2(const float* __restrict__ ew,
                           float* __restrict__ out) {
    int warp = (blockIdx.x * blockDim.x + threadIdx.x) >> 5;
    int lane = threadIdx.x & 31;
    if (warp >= N_EDGES) return;
    int s = 0, d = 0;
    float nrm = 0.f;
    if (lane == 0) {
        s = g_ei32[warp];
        d = g_ei32[N_EDGES + warp];
        nrm = g_dinv[s] * ew[warp] * g_dinv[d];
    }
    s   = __shfl_sync(0xffffffffu, s, 0);
    d   = __shfl_sync(0xffffffffu, d, 0);
    nrm = __shfl_sync(0xffffffffu, nrm, 0);

    const float2* ps = (const float2*)(g_p + (long long)s * OUT_F);
    float*        od = out + (long long)d * OUT_F;
    float2 v = ps[lane];
    atomicAdd(&od[lane * 2 + 0], v.x * nrm);
    atomicAdd(&od[lane * 2 + 1], v.y * nrm);
}

// ---------------------------------------------------------------------------
// fp32 SGEMM: C[M,N] = A[M,K] @ B[K,N] (+bias) (+relu)
// Double-buffered smem + register prefetch: global loads of tile k+1 overlap
// FMAs on tile k; one __syncthreads per K-step.
// BM=128 BN=64 BK=16, 256 threads, 8x4 per-thread tile.
template <int M_, int N_, int K_, bool RELU, bool BIAS, int ASEL, int CSEL>
__global__ __launch_bounds__(256)
void sgemm(const float* __restrict__ B, const float* __restrict__ bias) {
    constexpr int BM = 128, BN = 64, BK = 16, TM = 8, TN = 4;
    const float* A = buf<ASEL>();
    float*       C = buf<CSEL>();

    __shared__ float As[2][BK][BM + 4];
    __shared__ float Bs[2][BK][BN];

    const int tid  = threadIdx.x;
    const int brow = blockIdx.y * BM;
    const int bcol = blockIdx.x * BN;
    const int tcol = (tid % 16) * TN;   // 0..60
    const int trow = (tid / 16) * TM;   // 0..120

    float acc[TM][TN] = {};

    const int a_r = tid >> 2;           // 0..63
    const int a_c = (tid & 3) * 4;      // 0,4,8,12
    const int b_r = tid >> 4;           // 0..15
    const int b_c = (tid & 15) * 4;     // 0..60

    // ---- prologue: load tile k0=0 into buffer 0
    float4 av[2], bvp;
#pragma unroll
    for (int p = 0; p < 2; p++) {
        int row = brow + a_r + p * 64;
        av[p] = make_float4(0.f, 0.f, 0.f, 0.f);
        if (row < M_)
            av[p] = *(const float4*)(A + (long long)row * K_ + a_c);
    }
    bvp = *(const float4*)(B + (long long)b_r * N_ + bcol + b_c);
#pragma unroll
    for (int p = 0; p < 2; p++) {
        As[0][a_c + 0][a_r + p * 64] = av[p].x;
        As[0][a_c + 1][a_r + p * 64] = av[p].y;
        As[0][a_c + 2][a_r + p * 64] = av[p].z;
        As[0][a_c + 3][a_r + p * 64] = av[p].w;
    }
    *(float4*)&Bs[0][b_r][b_c] = bvp;
    __syncthreads();

    int cur = 0;
    for (int k0 = 0; k0 < K_; k0 += BK) {
        const bool has_next = (k0 + BK < K_);

        // prefetch next tile into registers (overlaps with FMAs below)
        if (has_next) {
#pragma unroll
            for (int p = 0; p < 2; p++) {
                int row = brow + a_r + p * 64;
                av[p] = make_float4(0.f, 0.f, 0.f, 0.f);
                if (row < M_)
                    av[p] = *(const float4*)(A + (long long)row * K_ + (k0 + BK) + a_c);
            }
            bvp = *(const float4*)(B + (long long)(k0 + BK + b_r) * N_ + bcol + b_c);
        }

        // compute on current buffer
#pragma unroll
        for (int kk = 0; kk < BK; kk++) {
            float4 a0 = *(const float4*)&As[cur][kk][trow];
            float4 a1 = *(const float4*)&As[cur][kk][trow + 4];
            float4 b0 = *(const float4*)&Bs[cur][kk][tcol];
            float ar[TM] = {a0.x, a0.y, a0.z, a0.w, a1.x, a1.y, a1.z, a1.w};
            float br[TN] = {b0.x, b0.y, b0.z, b0.w};
#pragma unroll
            for (int i = 0; i < TM; i++)
#pragma unroll
                for (int j = 0; j < TN; j++)
                    acc[i][j] += ar[i] * br[j];
        }

        // stage prefetched tile into the other buffer
        if (has_next) {
            int nxt = cur ^ 1;
#pragma unroll
            for (int p = 0; p < 2; p++) {
                As[nxt][a_c + 0][a_r + p * 64] = av[p].x;
                As[nxt][a_c + 1][a_r + p * 64] = av[p].y;
                As[nxt][a_c + 2][a_r + p * 64] = av[p].z;
                As[nxt][a_c + 3][a_r + p * 64] = av[p].w;
            }
            *(float4*)&Bs[nxt][b_r][b_c] = bvp;
            __syncthreads();
            cur = nxt;
        }
    }

    float4 bv = make_float4(0.f, 0.f, 0.f, 0.f);
    if (BIAS) bv = *(const float4*)(bias + bcol + tcol);
#pragma unroll
    for (int i = 0; i < TM; i++) {
        int row = brow + trow + i;
        if (row < M_) {
            float4 o;
            o.x = acc[i][0] + bv.x;
            o.y = acc[i][1] + bv.y;
            o.z = acc[i][2] + bv.z;
            o.w = acc[i][3] + bv.w;
            if (RELU) {
                o.x = fmaxf(o.x, 0.f); o.y = fmaxf(o.y, 0.f);
                o.z = fmaxf(o.z, 0.f); o.w = fmaxf(o.w, 0.f);
            }
            *(float4*)(C + (long long)row * N_ + bcol + tcol) = o;
        }
    }
}

// ---------------------------------------------------------------------------
extern "C" void kernel_launch(void* const* d_in, const int* in_sizes, int n_in,
                              void* d_out, int out_size) {
    const float* x  = (const float*)d_in[0];
    const int*   ei = (const int*)d_in[1];   // dtype resolved at runtime
    const float* ew = (const float*)d_in[2];
    const float* W1 = (const float*)d_in[3];
    const float* b1 = (const float*)d_in[4];
    const float* W2 = (const float*)d_in[5];
    const float* b2 = (const float*)d_in[6];
    float* out = (float*)d_out;

    const int T = 256;

    // 0) normalize edge_index dtype (int64 vs int32) into g_ei32
    k_detect<<<1, 512>>>(ei);
    k_convert<<<(2 * N_EDGES + T - 1) / T, T>>>(ei);

    // 1) degrees (with self-loop) -> dinv
    k_init_deg<<<(N_NODES + T - 1) / T, T>>>();
    k_deg_edges<<<(N_EDGES + T - 1) / T, T>>>(ew);
    k_dinv<<<(N_NODES + T - 1) / T, T>>>();

    // 2) g_agg1 = A_norm @ x   (self-loop init + edge scatter at 128 feats)
    {
        int total4 = N_NODES * (IN_F / 4);
        k_selfloop1<<<(total4 + T - 1) / T, T>>>(x);
        k_scatter1<<<(N_EDGES * 32 + T - 1) / T, T>>>(ew, x);
    }

    // 3) g_h1 = relu(g_agg1 @ W1 + b1)
    {
        dim3 grid(HID / 64, (N_NODES + 127) / 128);
        sgemm<N_NODES, HID, IN_F, true, true, 0, 1><<<grid, 256>>>(W1, b1);
    }

    // 4) g_p = g_h1 @ W2
    {
        dim3 grid(OUT_F / 64, (N_NODES + 127) / 128);
        sgemm<N_NODES, OUT_F, HID, false, false, 1, 2><<<grid, 256>>>(W2, nullptr);
    }

    // 5) out = A_norm @ g_p + b2  (self-loop init w/ bias + edge scatter at 64)
    {
        int total4 = N_NODES * (OUT_F / 4);
        k_selfloop2<<<(total4 + T - 1) / T, T>>>(b2, out);
        k_scatter2<<<(N_EDGES * 32 + T - 1) / T, T>>>(ew, out);
    }
}